// round 2
// baseline (speedup 1.0000x reference)
#include <cuda_runtime.h>
#include <cstdint>

typedef unsigned long long u64;

#define NB    64
#define CIN   256
#define PL    64
#define HH    56
#define WW    56
#define HW    3136
#define NPIX  200704   // NB*HW
#define NQUAD 50176    // NPIX/4
#define CNTD  200704.0
#define EPSD  1e-5

// ---------------- static device scratch ----------------
__device__ u64  g_w1b[64 * 4];
__device__ u64  g_w2b[64 * 9];
__device__ u64  g_w3b[256];
__device__ int4 g_s1v[NPIX * 8];   // conv1 outputs, int16 [pixel][64co]
__device__ int4 g_s2v[NPIX * 8];   // conv2 outputs, int16 [quad][4pix][64co]
__device__ u64  g_a1[NPIX];
__device__ ulonglong4 g_a2[NQUAD];
__device__ long long g_sum1[64], g_ss1[64];
__device__ long long g_sum2[64], g_ss2[64];
__device__ long long g_sum3[256], g_ss3[256];
__device__ float g_A3[256], g_B3[256];

// ---------------- K0: zero stats + pack weights ----------------
__global__ void k0_init(const float* __restrict__ w1,
                        const float* __restrict__ w2,
                        const float* __restrict__ w3) {
    const int t = threadIdx.x;   // 576 threads
    if (t < 64) {
        u64 wd0 = 0, wd1 = 0, wd2 = 0, wd3 = 0;
        const float* wp = w1 + t * 256;
        #pragma unroll 8
        for (int c = 0; c < 64; c++) wd0 |= (u64)(wp[c]       > 0.f) << c;
        #pragma unroll 8
        for (int c = 0; c < 64; c++) wd1 |= (u64)(wp[c + 64]  > 0.f) << c;
        #pragma unroll 8
        for (int c = 0; c < 64; c++) wd2 |= (u64)(wp[c + 128] > 0.f) << c;
        #pragma unroll 8
        for (int c = 0; c < 64; c++) wd3 |= (u64)(wp[c + 192] > 0.f) << c;
        g_w1b[t * 4 + 0] = wd0; g_w1b[t * 4 + 1] = wd1;
        g_w1b[t * 4 + 2] = wd2; g_w1b[t * 4 + 3] = wd3;
        g_sum1[t] = 0; g_ss1[t] = 0; g_sum2[t] = 0; g_ss2[t] = 0;
    }
    {   // w2 OIHW (64,64,3,3): bit over ci
        const int co = t / 9, tap = t - co * 9;
        u64 wd = 0;
        #pragma unroll 8
        for (int ci = 0; ci < 64; ci++)
            wd |= (u64)(w2[(co * 64 + ci) * 9 + tap] > 0.f) << ci;
        g_w2b[t] = wd;
    }
    if (t < 256) {
        u64 wd = 0;
        #pragma unroll 8
        for (int ci = 0; ci < 64; ci++)
            wd |= (u64)(w3[t * 64 + ci] > 0.f) << ci;
        g_w3b[t] = wd;
        g_sum3[t] = 0; g_ss3[t] = 0;
    }
}

// ---------------- K1: pack x, conv1 (1x1, 256->64), stats ----------------
__global__ __launch_bounds__(256) void k1_conv1(const float* __restrict__ x) {
    __shared__ u64 w1s[256];
    __shared__ int ssum[64], sss[64];
    const int tid = threadIdx.x;
    if (tid < 64) { ssum[tid] = 0; sss[tid] = 0; }
    w1s[tid] = g_w1b[tid];
    __syncthreads();

    const int p  = blockIdx.x * 256 + tid;   // exact: 784*256 = NPIX
    const int n  = p / HW;
    const int hw = p - n * HW;
    const float* xp = x + (size_t)n * CIN * HW + hw;

    u64 v0 = 0, v1 = 0, v2 = 0, v3 = 0;
    #pragma unroll 8
    for (int c = 0; c < 64; c++) v0 |= (u64)(xp[(size_t)c * HW] > 0.f) << c;
    xp += (size_t)64 * HW;
    #pragma unroll 8
    for (int c = 0; c < 64; c++) v1 |= (u64)(xp[(size_t)c * HW] > 0.f) << c;
    xp += (size_t)64 * HW;
    #pragma unroll 8
    for (int c = 0; c < 64; c++) v2 |= (u64)(xp[(size_t)c * HW] > 0.f) << c;
    xp += (size_t)64 * HW;
    #pragma unroll 8
    for (int c = 0; c < 64; c++) v3 |= (u64)(xp[(size_t)c * HW] > 0.f) << c;

    const int lane = tid & 31;
    short* out = reinterpret_cast<short*>(g_s1v) + (size_t)p * 64;

    #pragma unroll 1
    for (int g = 0; g < 8; g++) {
        int pk[4];
        #pragma unroll
        for (int jj = 0; jj < 4; jj++) {
            int sv0 = 0, sv1 = 0;
            #pragma unroll
            for (int k = 0; k < 2; k++) {
                const int co = g * 8 + jj * 2 + k;
                const u64* wq = &w1s[co * 4];
                int d = __popcll(v0 ^ wq[0]) + __popcll(v1 ^ wq[1])
                      + __popcll(v2 ^ wq[2]) + __popcll(v3 ^ wq[3]);
                int s = 256 - 2 * d;
                int rs = __reduce_add_sync(0xFFFFFFFFu, s);
                int rq = __reduce_add_sync(0xFFFFFFFFu, s * s);
                if (lane == 0) { atomicAdd(&ssum[co], rs); atomicAdd(&sss[co], rq); }
                if (k == 0) sv0 = s; else sv1 = s;
            }
            pk[jj] = (sv0 & 0xFFFF) | (sv1 << 16);
        }
        *reinterpret_cast<int4*>(out + g * 8) = make_int4(pk[0], pk[1], pk[2], pk[3]);
    }
    __syncthreads();
    if (tid < 64) {
        atomicAdd((u64*)&g_sum1[tid], (u64)(long long)ssum[tid]);
        atomicAdd((u64*)&g_ss1[tid],  (u64)(long long)sss[tid]);
    }
}

// ---------------- K2: BN1 threshold -> conv2 input bits ----------------
__global__ __launch_bounds__(256) void k2_bnpack1(const float* __restrict__ g1,
                                                  const float* __restrict__ b1) {
    __shared__ float As[64], Bs[64];
    const int tid = threadIdx.x;
    if (tid < 64) {
        double m   = (double)g_sum1[tid] / CNTD;
        double var = (double)g_ss1[tid] / CNTD - m * m;
        double r   = rsqrt(var + EPSD);
        double A   = (double)g1[tid] * r;
        As[tid] = (float)A;
        Bs[tid] = (float)((double)b1[tid] - A * m);
    }
    __syncthreads();
    const int p = blockIdx.x * 256 + tid;
    const short* sp = reinterpret_cast<const short*>(g_s1v) + (size_t)p * 64;
    u64 v = 0;
    #pragma unroll
    for (int g = 0; g < 8; g++) {
        int4 q = *reinterpret_cast<const int4*>(sp + g * 8);
        int arr[4] = {q.x, q.y, q.z, q.w};
        #pragma unroll
        for (int k = 0; k < 4; k++) {
            const int co = g * 8 + k * 2;
            float lo = (float)(short)arr[k];
            float hi = (float)(short)(arr[k] >> 16);
            v |= (u64)(fmaf(As[co],     lo, Bs[co])     > 0.f) << co;
            v |= (u64)(fmaf(As[co + 1], hi, Bs[co + 1]) > 0.f) << (co + 1);
        }
    }
    g_a1[p] = v;
}

// ---------------- K3: conv2 (3x3, pad 1) + stats; 4 horiz pixels/thread ----------------
__global__ __launch_bounds__(256) void k3_conv2() {
    __shared__ u64 w2s[576];
    __shared__ int ssum[64], sss[64];
    const int tid = threadIdx.x;
    if (tid < 64) { ssum[tid] = 0; sss[tid] = 0; }
    for (int i = tid; i < 576; i += 256) w2s[i] = g_w2b[i];
    __syncthreads();

    const int q  = blockIdx.x * 256 + tid;  // exact: 196*256 = NQUAD
    const int n  = q / 784;
    const int qi = q - n * 784;
    const int h  = (qi * 4) / 56;
    const int w  = (qi * 4) - h * 56;       // multiple of 4, <= 52

    bool rv[3], cv[6];
    #pragma unroll
    for (int r = 0; r < 3; r++) rv[r] = (unsigned)(h + r - 1) < 56u;
    #pragma unroll
    for (int c = 0; c < 6; c++) cv[c] = (unsigned)(w + c - 1) < 56u;

    u64 nb[3][6];
    const u64* ap = g_a1 + (size_t)n * HW;
    #pragma unroll
    for (int r = 0; r < 3; r++)
        #pragma unroll
        for (int c = 0; c < 6; c++)
            nb[r][c] = (rv[r] && cv[c]) ? ap[(h + r - 1) * 56 + (w + c - 1)] : 0ull;

    const int lane = tid & 31;
    short* out = reinterpret_cast<short*>(g_s2v) + (size_t)q * 256;

    #pragma unroll 1
    for (int g = 0; g < 8; g++) {
        int pk[4][4];
        #pragma unroll
        for (int jj = 0; jj < 4; jj++) {
            int se[4], so[4];
            #pragma unroll
            for (int k = 0; k < 2; k++) {
                const int co = g * 8 + jj * 2 + k;
                u64 wv[9];
                #pragma unroll
                for (int t = 0; t < 9; t++) wv[t] = w2s[co * 9 + t];
                int s[4];
                #pragma unroll
                for (int j = 0; j < 4; j++) {
                    int acc = 0;
                    #pragma unroll
                    for (int kh = 0; kh < 3; kh++)
                        #pragma unroll
                        for (int kw = 0; kw < 3; kw++)
                            if (rv[kh] && cv[j + kw])
                                acc += 64 - 2 * __popcll(nb[kh][j + kw] ^ wv[kh * 3 + kw]);
                    s[j] = acc;
                }
                int rs = __reduce_add_sync(0xFFFFFFFFu, s[0] + s[1] + s[2] + s[3]);
                int rq = __reduce_add_sync(0xFFFFFFFFu,
                          s[0]*s[0] + s[1]*s[1] + s[2]*s[2] + s[3]*s[3]);
                if (lane == 0) { atomicAdd(&ssum[co], rs); atomicAdd(&sss[co], rq); }
                #pragma unroll
                for (int j = 0; j < 4; j++) { if (k == 0) se[j] = s[j]; else so[j] = s[j]; }
            }
            #pragma unroll
            for (int j = 0; j < 4; j++)
                pk[j][jj] = (se[j] & 0xFFFF) | (so[j] << 16);
        }
        #pragma unroll
        for (int j = 0; j < 4; j++)
            *reinterpret_cast<int4*>(out + j * 64 + g * 8) =
                make_int4(pk[j][0], pk[j][1], pk[j][2], pk[j][3]);
    }
    __syncthreads();
    if (tid < 64) {
        atomicAdd((u64*)&g_sum2[tid], (u64)(long long)ssum[tid]);
        atomicAdd((u64*)&g_ss2[tid],  (u64)(long long)sss[tid]);
    }
}

// ---------------- K4: BN2 threshold -> conv3 bits + conv3 stats ----------------
__global__ __launch_bounds__(256) void k4_pack2_c3(const float* __restrict__ g2,
                                                   const float* __restrict__ b2) {
    __shared__ float As[64], Bs[64];
    __shared__ u64 w3s[256];
    __shared__ int ssum[256], sss[256];
    const int tid = threadIdx.x;
    if (tid < 64) {
        double m   = (double)g_sum2[tid] / CNTD;
        double var = (double)g_ss2[tid] / CNTD - m * m;
        double r   = rsqrt(var + EPSD);
        double A   = (double)g2[tid] * r;
        As[tid] = (float)A;
        Bs[tid] = (float)((double)b2[tid] - A * m);
    }
    w3s[tid] = g_w3b[tid];
    ssum[tid] = 0; sss[tid] = 0;
    __syncthreads();

    const int q = blockIdx.x * 256 + tid;   // exact NQUAD
    const short* sp = reinterpret_cast<const short*>(g_s2v) + (size_t)q * 256;

    u64 v[4];
    #pragma unroll
    for (int j = 0; j < 4; j++) {
        u64 vv = 0;
        #pragma unroll
        for (int g = 0; g < 8; g++) {
            int4 qq = *reinterpret_cast<const int4*>(sp + j * 64 + g * 8);
            int arr[4] = {qq.x, qq.y, qq.z, qq.w};
            #pragma unroll
            for (int k = 0; k < 4; k++) {
                const int co = g * 8 + k * 2;
                float lo = (float)(short)arr[k];
                float hi = (float)(short)(arr[k] >> 16);
                vv |= (u64)(fmaf(As[co],     lo, Bs[co])     > 0.f) << co;
                vv |= (u64)(fmaf(As[co + 1], hi, Bs[co + 1]) > 0.f) << (co + 1);
            }
        }
        v[j] = vv;
    }
    g_a2[q] = make_ulonglong4(v[0], v[1], v[2], v[3]);

    const int lane = tid & 31;
    #pragma unroll 4
    for (int co = 0; co < 256; co++) {
        const u64 wv = w3s[co];
        int t0 = 64 - 2 * __popcll(v[0] ^ wv);
        int t1 = 64 - 2 * __popcll(v[1] ^ wv);
        int t2 = 64 - 2 * __popcll(v[2] ^ wv);
        int t3 = 64 - 2 * __popcll(v[3] ^ wv);
        int rs = __reduce_add_sync(0xFFFFFFFFu, t0 + t1 + t2 + t3);
        int rq = __reduce_add_sync(0xFFFFFFFFu, t0*t0 + t1*t1 + t2*t2 + t3*t3);
        if (lane == 0) { atomicAdd(&ssum[co], rs); atomicAdd(&sss[co], rq); }
    }
    __syncthreads();
    atomicAdd((u64*)&g_sum3[tid], (u64)(long long)ssum[tid]);
    atomicAdd((u64*)&g_ss3[tid],  (u64)(long long)sss[tid]);
}

// ---------------- K5: finalize BN3 affine ----------------
__global__ void k5_fin3(const float* __restrict__ g3, const float* __restrict__ b3) {
    const int c = threadIdx.x;   // 256 threads
    double m   = (double)g_sum3[c] / CNTD;
    double var = (double)g_ss3[c] / CNTD - m * m;
    double r   = rsqrt(var + EPSD);
    double A   = (double)g3[c] * r;
    g_A3[c] = (float)A;
    g_B3[c] = (float)((double)b3[c] - A * m);
}

// ---------------- K6: conv3 recompute + BN3 + residual + hardtanh ----------------
__global__ __launch_bounds__(256) void k6_final(const float* __restrict__ x,
                                                float* __restrict__ out) {
    __shared__ u64 w3s[8];
    __shared__ float As[8], Bs[8];
    const int tid = threadIdx.x;
    const int cg  = blockIdx.y;          // 32 channel groups of 8
    if (tid < 8) {
        w3s[tid] = g_w3b[cg * 8 + tid];
        As[tid]  = g_A3[cg * 8 + tid];
        Bs[tid]  = g_B3[cg * 8 + tid];
    }
    __syncthreads();

    const int q  = blockIdx.x * 256 + tid;   // exact NQUAD
    const int n  = q / 784;
    const int hw = (q - n * 784) * 4;
    ulonglong4 a = g_a2[q];
    u64 av0 = a.x, av1 = a.y, av2 = a.z, av3 = a.w;

    const size_t base = ((size_t)n * CIN + (size_t)cg * 8) * HW + hw;
    #pragma unroll
    for (int k = 0; k < 8; k++) {
        const u64 wv = w3s[k];
        const float A = As[k], B = Bs[k];
        float4 xv = *reinterpret_cast<const float4*>(x + base + (size_t)k * HW);
        float4 o;
        o.x = fminf(fmaxf(fmaf(A, (float)(64 - 2 * __popcll(av0 ^ wv)), B) + xv.x, -1.f), 1.f);
        o.y = fminf(fmaxf(fmaf(A, (float)(64 - 2 * __popcll(av1 ^ wv)), B) + xv.y, -1.f), 1.f);
        o.z = fminf(fmaxf(fmaf(A, (float)(64 - 2 * __popcll(av2 ^ wv)), B) + xv.z, -1.f), 1.f);
        o.w = fminf(fmaxf(fmaf(A, (float)(64 - 2 * __popcll(av3 ^ wv)), B) + xv.w, -1.f), 1.f);
        *reinterpret_cast<float4*>(out + base + (size_t)k * HW) = o;
    }
}

extern "C" void kernel_launch(void* const* d_in, const int* in_sizes, int n_in,
                              void* d_out, int out_size) {
    const float* x  = (const float*)d_in[0];
    const float* w1 = (const float*)d_in[1];
    const float* w2 = (const float*)d_in[2];
    const float* w3 = (const float*)d_in[3];
    const float* g1 = (const float*)d_in[4];
    const float* b1 = (const float*)d_in[5];
    const float* g2 = (const float*)d_in[6];
    const float* b2 = (const float*)d_in[7];
    const float* g3 = (const float*)d_in[8];
    const float* b3 = (const float*)d_in[9];
    float* out = (float*)d_out;

    k0_init<<<1, 576>>>(w1, w2, w3);
    k1_conv1<<<784, 256>>>(x);
    k2_bnpack1<<<784, 256>>>(g1, b1);
    k3_conv2<<<196, 256>>>();
    k4_pack2_c3<<<196, 256>>>(g2, b2);
    k5_fin3<<<1, 256>>>(g3, b3);
    dim3 g6(196, 32);
    k6_final<<<g6, 256>>>(x, out);
}

// round 3
// speedup vs baseline: 1.0694x; 1.0694x over previous
#include <cuda_runtime.h>
#include <cstdint>

typedef unsigned long long u64;

#define NB    64
#define CIN   256
#define PL    64
#define HH    56
#define WW    56
#define HW    3136
#define NPIX  200704   // NB*HW
#define NQUAD 50176    // NPIX/4
#define CNTD  200704.0
#define EPSD  1e-5
#define PADW  58
#define PADHW 3364     // 58*58

// ---------------- static device scratch ----------------
__device__ u64  g_w1b[64 * 4];
__device__ u64  g_w2b[64 * 9];
__device__ u64  g_w3b[256];
__device__ int  g_ctab[9 * 64];       // border-pattern corrections for conv2
__device__ int4 g_s1v[8 * NPIX];      // conv1 outputs int16, [group][pixel]
__device__ int4 g_s2v[8 * NPIX];      // conv2 outputs int16, [group][pixel]
__device__ u64  g_a1p[NB * PADHW];    // conv2 input bits, zero halo (zero-init, halo never written)
__device__ ulonglong4 g_a2[NQUAD];    // conv3 input bits (pixel-major u64, quad views)
__device__ long long g_sum1[64], g_ss1[64];
__device__ long long g_sum2[64], g_ss2[64];
__device__ long long g_sum3[256], g_ss3[256];
__device__ float g_A3[256], g_B3[256];

// ---------------- K0: zero stats + pack weights + border table ----------------
__global__ void k0_init(const float* __restrict__ w1,
                        const float* __restrict__ w2,
                        const float* __restrict__ w3) {
    const int t = threadIdx.x;   // 576 threads
    if (t < 64) {
        u64 wd0 = 0, wd1 = 0, wd2 = 0, wd3 = 0;
        const float* wp = w1 + t * 256;
        #pragma unroll 8
        for (int c = 0; c < 64; c++) wd0 |= (u64)(wp[c]       > 0.f) << c;
        #pragma unroll 8
        for (int c = 0; c < 64; c++) wd1 |= (u64)(wp[c + 64]  > 0.f) << c;
        #pragma unroll 8
        for (int c = 0; c < 64; c++) wd2 |= (u64)(wp[c + 128] > 0.f) << c;
        #pragma unroll 8
        for (int c = 0; c < 64; c++) wd3 |= (u64)(wp[c + 192] > 0.f) << c;
        g_w1b[t * 4 + 0] = wd0; g_w1b[t * 4 + 1] = wd1;
        g_w1b[t * 4 + 2] = wd2; g_w1b[t * 4 + 3] = wd3;
        g_sum1[t] = 0; g_ss1[t] = 0; g_sum2[t] = 0; g_ss2[t] = 0;
    }
    {   // w2 OIHW (64,64,3,3)
        const int co = t / 9, tap = t - co * 9;
        u64 wd = 0;
        #pragma unroll 8
        for (int ci = 0; ci < 64; ci++)
            wd |= (u64)(w2[(co * 64 + ci) * 9 + tap] > 0.f) << ci;
        g_w2b[t] = wd;
    }
    if (t < 256) {
        u64 wd = 0;
        #pragma unroll 8
        for (int ci = 0; ci < 64; ci++)
            wd |= (u64)(w3[t * 64 + ci] > 0.f) << ci;
        g_w3b[t] = wd;
        g_sum3[t] = 0; g_ss3[t] = 0;
    }
    __syncthreads();
    // Correction table: pattern pid = rowcase*3+colcase; entry = sum over
    // invalid taps of (64 - 2*popc(w2_tap)) (what a zero halo word wrongly adds).
    {
        const int pid = t / 64, co = t - pid * 64;  // t<576 -> pid<9
        const int rowc = pid / 3, colc = pid - rowc * 3;
        int corr = 0;
        #pragma unroll
        for (int tap = 0; tap < 9; tap++) {
            const int r = tap / 3, c = tap - r * 3;
            bool inval = (rowc == 1 && r == 0) || (rowc == 2 && r == 2) ||
                         (colc == 1 && c == 0) || (colc == 2 && c == 2);
            if (inval) corr += 64 - 2 * __popcll(g_w2b[co * 9 + tap]);
        }
        g_ctab[t] = corr;
    }
}

// ---------------- K1: pack x, conv1 (1x1, 256->64), stats ----------------
__global__ __launch_bounds__(256) void k1_conv1(const float* __restrict__ x) {
    __shared__ u64 w1s[256];
    __shared__ int ssum[64], sss[64];
    const int tid = threadIdx.x;
    if (tid < 64) { ssum[tid] = 0; sss[tid] = 0; }
    w1s[tid] = g_w1b[tid];
    __syncthreads();

    const int p  = blockIdx.x * 256 + tid;   // 784*256 = NPIX
    const int n  = p / HW;
    const int hw = p - n * HW;
    const float* xp = x + (size_t)n * CIN * HW + hw;

    u64 v0 = 0, v1 = 0, v2 = 0, v3 = 0;
    #pragma unroll 8
    for (int c = 0; c < 64; c++) v0 |= (u64)(xp[(size_t)c * HW] > 0.f) << c;
    xp += (size_t)64 * HW;
    #pragma unroll 8
    for (int c = 0; c < 64; c++) v1 |= (u64)(xp[(size_t)c * HW] > 0.f) << c;
    xp += (size_t)64 * HW;
    #pragma unroll 8
    for (int c = 0; c < 64; c++) v2 |= (u64)(xp[(size_t)c * HW] > 0.f) << c;
    xp += (size_t)64 * HW;
    #pragma unroll 8
    for (int c = 0; c < 64; c++) v3 |= (u64)(xp[(size_t)c * HW] > 0.f) << c;

    const int lane = tid & 31;

    #pragma unroll 1
    for (int g = 0; g < 8; g++) {
        int pk[4];
        #pragma unroll
        for (int jj = 0; jj < 4; jj++) {
            int sv0 = 0, sv1 = 0;
            #pragma unroll
            for (int k = 0; k < 2; k++) {
                const int co = g * 8 + jj * 2 + k;
                const u64* wq = &w1s[co * 4];
                int d = __popcll(v0 ^ wq[0]) + __popcll(v1 ^ wq[1])
                      + __popcll(v2 ^ wq[2]) + __popcll(v3 ^ wq[3]);
                int s = 256 - 2 * d;
                int rs = __reduce_add_sync(0xFFFFFFFFu, s);
                int rq = __reduce_add_sync(0xFFFFFFFFu, s * s);
                if (lane == 0) { atomicAdd(&ssum[co], rs); atomicAdd(&sss[co], rq); }
                if (k == 0) sv0 = s; else sv1 = s;
            }
            pk[jj] = (sv0 & 0xFFFF) | (sv1 << 16);
        }
        g_s1v[g * NPIX + p] = make_int4(pk[0], pk[1], pk[2], pk[3]);
    }
    __syncthreads();
    if (tid < 64) {
        atomicAdd((u64*)&g_sum1[tid], (u64)(long long)ssum[tid]);
        atomicAdd((u64*)&g_ss1[tid],  (u64)(long long)sss[tid]);
    }
}

// ---------------- K2: BN1 threshold -> padded conv2 input bits ----------------
__global__ __launch_bounds__(256) void k2_bnpack1(const float* __restrict__ g1,
                                                  const float* __restrict__ b1) {
    __shared__ float As[64], Bs[64];
    const int tid = threadIdx.x;
    if (tid < 64) {
        double m   = (double)g_sum1[tid] / CNTD;
        double var = (double)g_ss1[tid] / CNTD - m * m;
        double r   = rsqrt(var + EPSD);
        double A   = (double)g1[tid] * r;
        As[tid] = (float)A;
        Bs[tid] = (float)((double)b1[tid] - A * m);
    }
    __syncthreads();
    const int p = blockIdx.x * 256 + tid;
    u64 v = 0;
    #pragma unroll
    for (int g = 0; g < 8; g++) {
        int4 q = g_s1v[g * NPIX + p];
        int arr[4] = {q.x, q.y, q.z, q.w};
        #pragma unroll
        for (int k = 0; k < 4; k++) {
            const int co = g * 8 + k * 2;
            float lo = (float)(short)arr[k];
            float hi = (float)(short)(arr[k] >> 16);
            v |= (u64)(fmaf(As[co],     lo, Bs[co])     > 0.f) << co;
            v |= (u64)(fmaf(As[co + 1], hi, Bs[co + 1]) > 0.f) << (co + 1);
        }
    }
    const int n  = p / HW;
    const int hw = p - n * HW;
    const int h  = hw / WW;
    const int w  = hw - h * WW;
    g_a1p[(size_t)n * PADHW + (size_t)(h + 1) * PADW + (w + 1)] = v;
}

// ---------------- K3: conv2 (3x3, pad 1) + stats; 1 pixel/thread ----------------
__global__ __launch_bounds__(256) void k3_conv2() {
    __shared__ u64 w2s[576];
    __shared__ int ctab[576];
    __shared__ int ssum[64], sss[64];
    const int tid = threadIdx.x;
    if (tid < 64) { ssum[tid] = 0; sss[tid] = 0; }
    for (int i = tid; i < 576; i += 256) { w2s[i] = g_w2b[i]; ctab[i] = g_ctab[i]; }
    __syncthreads();

    const int p  = blockIdx.x * 256 + tid;  // 784 blocks
    const int n  = p / HW;
    const int hw = p - n * HW;
    const int h  = hw / WW;
    const int w  = hw - h * WW;

    const u64* ap = g_a1p + (size_t)n * PADHW + (size_t)h * PADW + w;
    u64 nb0 = ap[0],        nb1 = ap[1],        nb2 = ap[2];
    u64 nb3 = ap[PADW],     nb4 = ap[PADW + 1], nb5 = ap[PADW + 2];
    u64 nb6 = ap[2 * PADW], nb7 = ap[2 * PADW + 1], nb8 = ap[2 * PADW + 2];

    const int rowc = (h == 0) ? 1 : ((h == HH - 1) ? 2 : 0);
    const int colc = (w == 0) ? 1 : ((w == WW - 1) ? 2 : 0);
    const int* crow = &ctab[(rowc * 3 + colc) * 64];

    const int lane = tid & 31;

    #pragma unroll 1
    for (int g = 0; g < 8; g++) {
        int pk[4];
        #pragma unroll
        for (int jj = 0; jj < 4; jj++) {
            int sv0 = 0, sv1 = 0;
            #pragma unroll
            for (int k = 0; k < 2; k++) {
                const int co = g * 8 + jj * 2 + k;
                const u64* wv = &w2s[co * 9];
                int d = __popcll(nb0 ^ wv[0]) + __popcll(nb1 ^ wv[1]) + __popcll(nb2 ^ wv[2])
                      + __popcll(nb3 ^ wv[3]) + __popcll(nb4 ^ wv[4]) + __popcll(nb5 ^ wv[5])
                      + __popcll(nb6 ^ wv[6]) + __popcll(nb7 ^ wv[7]) + __popcll(nb8 ^ wv[8]);
                int s = 576 - 2 * d - crow[co];
                int rs = __reduce_add_sync(0xFFFFFFFFu, s);
                int rq = __reduce_add_sync(0xFFFFFFFFu, s * s);
                if (lane == 0) { atomicAdd(&ssum[co], rs); atomicAdd(&sss[co], rq); }
                if (k == 0) sv0 = s; else sv1 = s;
            }
            pk[jj] = (sv0 & 0xFFFF) | (sv1 << 16);
        }
        g_s2v[g * NPIX + p] = make_int4(pk[0], pk[1], pk[2], pk[3]);
    }
    __syncthreads();
    if (tid < 64) {
        atomicAdd((u64*)&g_sum2[tid], (u64)(long long)ssum[tid]);
        atomicAdd((u64*)&g_ss2[tid],  (u64)(long long)sss[tid]);
    }
}

// ---------------- K4: BN2 threshold -> conv3 bits + conv3 stats ----------------
__global__ __launch_bounds__(256) void k4_pack2_c3(const float* __restrict__ g2,
                                                   const float* __restrict__ b2) {
    __shared__ float As[64], Bs[64];
    __shared__ u64 w3s[256];
    __shared__ int ssum[256], sss[256];
    const int tid = threadIdx.x;
    if (tid < 64) {
        double m   = (double)g_sum2[tid] / CNTD;
        double var = (double)g_ss2[tid] / CNTD - m * m;
        double r   = rsqrt(var + EPSD);
        double A   = (double)g2[tid] * r;
        As[tid] = (float)A;
        Bs[tid] = (float)((double)b2[tid] - A * m);
    }
    w3s[tid] = g_w3b[tid];
    ssum[tid] = 0; sss[tid] = 0;
    __syncthreads();

    const int p = blockIdx.x * 256 + tid;   // 784 blocks
    u64 v = 0;
    #pragma unroll
    for (int g = 0; g < 8; g++) {
        int4 qq = g_s2v[g * NPIX + p];
        int arr[4] = {qq.x, qq.y, qq.z, qq.w};
        #pragma unroll
        for (int k = 0; k < 4; k++) {
            const int co = g * 8 + k * 2;
            float lo = (float)(short)arr[k];
            float hi = (float)(short)(arr[k] >> 16);
            v |= (u64)(fmaf(As[co],     lo, Bs[co])     > 0.f) << co;
            v |= (u64)(fmaf(As[co + 1], hi, Bs[co + 1]) > 0.f) << (co + 1);
        }
    }
    reinterpret_cast<u64*>(g_a2)[p] = v;

    const int lane = tid & 31;
    #pragma unroll 4
    for (int co = 0; co < 256; co++) {
        int t = 64 - 2 * __popcll(v ^ w3s[co]);
        int rs = __reduce_add_sync(0xFFFFFFFFu, t);
        int rq = __reduce_add_sync(0xFFFFFFFFu, t * t);
        if (lane == 0) { atomicAdd(&ssum[co], rs); atomicAdd(&sss[co], rq); }
    }
    __syncthreads();
    atomicAdd((u64*)&g_sum3[tid], (u64)(long long)ssum[tid]);
    atomicAdd((u64*)&g_ss3[tid],  (u64)(long long)sss[tid]);
}

// ---------------- K5: finalize BN3 affine ----------------
__global__ void k5_fin3(const float* __restrict__ g3, const float* __restrict__ b3) {
    const int c = threadIdx.x;   // 256 threads
    double m   = (double)g_sum3[c] / CNTD;
    double var = (double)g_ss3[c] / CNTD - m * m;
    double r   = rsqrt(var + EPSD);
    double A   = (double)g3[c] * r;
    g_A3[c] = (float)A;
    g_B3[c] = (float)((double)b3[c] - A * m);
}

// ---------------- K6: conv3 recompute + BN3 + residual + hardtanh ----------------
__global__ __launch_bounds__(256) void k6_final(const float* __restrict__ x,
                                                float* __restrict__ out) {
    __shared__ u64 w3s[8];
    __shared__ float As[8], Bs[8];
    const int tid = threadIdx.x;
    const int cg  = blockIdx.y;          // 32 channel groups of 8
    if (tid < 8) {
        w3s[tid] = g_w3b[cg * 8 + tid];
        As[tid]  = g_A3[cg * 8 + tid];
        Bs[tid]  = g_B3[cg * 8 + tid];
    }
    __syncthreads();

    const int q  = blockIdx.x * 256 + tid;   // NQUAD
    const int n  = q / 784;
    const int hw = (q - n * 784) * 4;
    ulonglong4 a = g_a2[q];
    u64 av0 = a.x, av1 = a.y, av2 = a.z, av3 = a.w;

    const size_t base = ((size_t)n * CIN + (size_t)cg * 8) * HW + hw;
    #pragma unroll
    for (int k = 0; k < 8; k++) {
        const u64 wv = w3s[k];
        const float A = As[k], B = Bs[k];
        float4 xv = *reinterpret_cast<const float4*>(x + base + (size_t)k * HW);
        float4 o;
        o.x = fminf(fmaxf(fmaf(A, (float)(64 - 2 * __popcll(av0 ^ wv)), B) + xv.x, -1.f), 1.f);
        o.y = fminf(fmaxf(fmaf(A, (float)(64 - 2 * __popcll(av1 ^ wv)), B) + xv.y, -1.f), 1.f);
        o.z = fminf(fmaxf(fmaf(A, (float)(64 - 2 * __popcll(av2 ^ wv)), B) + xv.z, -1.f), 1.f);
        o.w = fminf(fmaxf(fmaf(A, (float)(64 - 2 * __popcll(av3 ^ wv)), B) + xv.w, -1.f), 1.f);
        *reinterpret_cast<float4*>(out + base + (size_t)k * HW) = o;
    }
}

extern "C" void kernel_launch(void* const* d_in, const int* in_sizes, int n_in,
                              void* d_out, int out_size) {
    const float* x  = (const float*)d_in[0];
    const float* w1 = (const float*)d_in[1];
    const float* w2 = (const float*)d_in[2];
    const float* w3 = (const float*)d_in[3];
    const float* g1 = (const float*)d_in[4];
    const float* b1 = (const float*)d_in[5];
    const float* g2 = (const float*)d_in[6];
    const float* b2 = (const float*)d_in[7];
    const float* g3 = (const float*)d_in[8];
    const float* b3 = (const float*)d_in[9];
    float* out = (float*)d_out;

    k0_init<<<1, 576>>>(w1, w2, w3);
    k1_conv1<<<784, 256>>>(x);
    k2_bnpack1<<<784, 256>>>(g1, b1);
    k3_conv2<<<784, 256>>>();
    k4_pack2_c3<<<784, 256>>>(g2, b2);
    k5_fin3<<<1, 256>>>(g3, b3);
    dim3 g6(196, 32);
    k6_final<<<g6, 256>>>(x, out);
}

// round 4
// speedup vs baseline: 1.1527x; 1.0779x over previous
#include <cuda_runtime.h>
#include <cstdint>

typedef unsigned long long u64;

#define NB    64
#define CIN   256
#define HH    56
#define WW    56
#define HW    3136
#define NPIX  200704   // NB*HW
#define NQUAD 50176    // NPIX/4
#define CNTD  200704.0
#define EPSD  1e-5
#define PADW  58
#define PADHW 3364     // 58*58

// ---------------- static device scratch ----------------
__device__ u64  g_w1b[64 * 4];
__device__ u64  g_w2b[64 * 9];
__device__ u64  g_w3b[256];
__device__ int  g_ctab[9 * 64];       // border-pattern corrections for conv2
__device__ int4 g_s1v[8 * NPIX];      // conv1 outputs int16, [group][pixel]
__device__ short g_s2[NPIX * 64];     // conv2 outputs int16, [pixel][ch]
__device__ u64  g_a1p[NB * PADHW];    // conv2 input bits, zero halo (zero-init, halo never written)
__device__ ulonglong4 g_a2[NQUAD];    // conv3 input bits (pixel-major u64, quad views)
__device__ long long g_sum1[64], g_ss1[64];
__device__ long long g_sum2[64], g_ss2[64];
__device__ long long g_sum3[256], g_ss3[256];
__device__ float g_A3[256], g_B3[256];

// ---------------- K0: zero stats + pack weights + border table ----------------
__global__ void k0_init(const float* __restrict__ w1,
                        const float* __restrict__ w2,
                        const float* __restrict__ w3) {
    const int t = threadIdx.x;   // 576 threads
    if (t < 64) {
        u64 wd0 = 0, wd1 = 0, wd2 = 0, wd3 = 0;
        const float* wp = w1 + t * 256;
        #pragma unroll 8
        for (int c = 0; c < 64; c++) wd0 |= (u64)(wp[c]       > 0.f) << c;
        #pragma unroll 8
        for (int c = 0; c < 64; c++) wd1 |= (u64)(wp[c + 64]  > 0.f) << c;
        #pragma unroll 8
        for (int c = 0; c < 64; c++) wd2 |= (u64)(wp[c + 128] > 0.f) << c;
        #pragma unroll 8
        for (int c = 0; c < 64; c++) wd3 |= (u64)(wp[c + 192] > 0.f) << c;
        g_w1b[t * 4 + 0] = wd0; g_w1b[t * 4 + 1] = wd1;
        g_w1b[t * 4 + 2] = wd2; g_w1b[t * 4 + 3] = wd3;
        g_sum1[t] = 0; g_ss1[t] = 0; g_sum2[t] = 0; g_ss2[t] = 0;
    }
    {   // w2 OIHW (64,64,3,3)
        const int co = t / 9, tap = t - co * 9;
        u64 wd = 0;
        #pragma unroll 8
        for (int ci = 0; ci < 64; ci++)
            wd |= (u64)(w2[(co * 64 + ci) * 9 + tap] > 0.f) << ci;
        g_w2b[t] = wd;
    }
    if (t < 256) {
        u64 wd = 0;
        #pragma unroll 8
        for (int ci = 0; ci < 64; ci++)
            wd |= (u64)(w3[t * 64 + ci] > 0.f) << ci;
        g_w3b[t] = wd;
        g_sum3[t] = 0; g_ss3[t] = 0;
    }
    __syncthreads();
    // Correction table: pattern pid = rowcase*3+colcase; entry = sum over
    // invalid taps of (64 - 2*popc(w2_tap)) (what a zero halo word wrongly adds).
    {
        const int pid = t / 64, co = t - pid * 64;  // t<576 -> pid<9
        const int rowc = pid / 3, colc = pid - rowc * 3;
        int corr = 0;
        #pragma unroll
        for (int tap = 0; tap < 9; tap++) {
            const int r = tap / 3, c = tap - r * 3;
            bool inval = (rowc == 1 && r == 0) || (rowc == 2 && r == 2) ||
                         (colc == 1 && c == 0) || (colc == 2 && c == 2);
            if (inval) corr += 64 - 2 * __popcll(g_w2b[co * 9 + tap]);
        }
        g_ctab[t] = corr;
    }
}

// ---------------- K1: pack x, conv1 (1x1, 256->64), stats ----------------
__global__ __launch_bounds__(256) void k1_conv1(const float* __restrict__ x) {
    __shared__ u64 w1s[256];
    __shared__ int ssum[64], sss[64];
    const int tid = threadIdx.x;
    if (tid < 64) { ssum[tid] = 0; sss[tid] = 0; }
    w1s[tid] = g_w1b[tid];
    __syncthreads();

    const int p  = blockIdx.x * 256 + tid;   // 784*256 = NPIX
    const int n  = p / HW;
    const int hw = p - n * HW;
    const float* xp = x + (size_t)n * CIN * HW + hw;

    u64 v0 = 0, v1 = 0, v2 = 0, v3 = 0;
    #pragma unroll 8
    for (int c = 0; c < 64; c++) v0 |= (u64)(xp[(size_t)c * HW] > 0.f) << c;
    xp += (size_t)64 * HW;
    #pragma unroll 8
    for (int c = 0; c < 64; c++) v1 |= (u64)(xp[(size_t)c * HW] > 0.f) << c;
    xp += (size_t)64 * HW;
    #pragma unroll 8
    for (int c = 0; c < 64; c++) v2 |= (u64)(xp[(size_t)c * HW] > 0.f) << c;
    xp += (size_t)64 * HW;
    #pragma unroll 8
    for (int c = 0; c < 64; c++) v3 |= (u64)(xp[(size_t)c * HW] > 0.f) << c;

    const int lane = tid & 31;

    #pragma unroll 1
    for (int g = 0; g < 8; g++) {
        int pk[4];
        #pragma unroll
        for (int jj = 0; jj < 4; jj++) {
            int sv0 = 0, sv1 = 0;
            #pragma unroll
            for (int k = 0; k < 2; k++) {
                const int co = g * 8 + jj * 2 + k;
                const u64* wq = &w1s[co * 4];
                int d = __popcll(v0 ^ wq[0]) + __popcll(v1 ^ wq[1])
                      + __popcll(v2 ^ wq[2]) + __popcll(v3 ^ wq[3]);
                int s = 256 - 2 * d;
                int rs = __reduce_add_sync(0xFFFFFFFFu, s);
                int rq = __reduce_add_sync(0xFFFFFFFFu, s * s);
                if (lane == 0) { atomicAdd(&ssum[co], rs); atomicAdd(&sss[co], rq); }
                if (k == 0) sv0 = s; else sv1 = s;
            }
            pk[jj] = (sv0 & 0xFFFF) | (sv1 << 16);
        }
        g_s1v[g * NPIX + p] = make_int4(pk[0], pk[1], pk[2], pk[3]);
    }
    __syncthreads();
    if (tid < 64) {
        atomicAdd((u64*)&g_sum1[tid], (u64)(long long)ssum[tid]);
        atomicAdd((u64*)&g_ss1[tid],  (u64)(long long)sss[tid]);
    }
}

// ---------------- K2: BN1 threshold -> padded conv2 input bits ----------------
__global__ __launch_bounds__(256) void k2_bnpack1(const float* __restrict__ g1,
                                                  const float* __restrict__ b1) {
    __shared__ float As[64], Bs[64];
    const int tid = threadIdx.x;
    if (tid < 64) {
        double m   = (double)g_sum1[tid] / CNTD;
        double var = (double)g_ss1[tid] / CNTD - m * m;
        double r   = rsqrt(var + EPSD);
        double A   = (double)g1[tid] * r;
        As[tid] = (float)A;
        Bs[tid] = (float)((double)b1[tid] - A * m);
    }
    __syncthreads();
    const int p = blockIdx.x * 256 + tid;
    u64 v = 0;
    #pragma unroll
    for (int g = 0; g < 8; g++) {
        int4 q = g_s1v[g * NPIX + p];
        int arr[4] = {q.x, q.y, q.z, q.w};
        #pragma unroll
        for (int k = 0; k < 4; k++) {
            const int co = g * 8 + k * 2;
            float lo = (float)(short)arr[k];
            float hi = (float)(short)(arr[k] >> 16);
            v |= (u64)(fmaf(As[co],     lo, Bs[co])     > 0.f) << co;
            v |= (u64)(fmaf(As[co + 1], hi, Bs[co + 1]) > 0.f) << (co + 1);
        }
    }
    const int n  = p / HW;
    const int hw = p - n * HW;
    const int h  = hw / WW;
    const int w  = hw - h * WW;
    g_a1p[(size_t)n * PADHW + (size_t)(h + 1) * PADW + (w + 1)] = v;
}

// ---------------- K3: conv2 (3x3, pad 1) + stats; warp = (row, channel-half) ----------------
// Lane = channel: 9 weights live in registers, window slides along the row via
// uniform L1-hot loads. Stats accumulate per-lane (per-channel) in registers.
__global__ __launch_bounds__(256) void k3_conv2() {
    __shared__ int bsum[64], bsq[64];
    const int tid  = threadIdx.x;
    const int wid  = tid >> 5;
    const int lane = tid & 31;
    if (tid < 64) { bsum[tid] = 0; bsq[tid] = 0; }
    __syncthreads();

    const int job  = blockIdx.x * 8 + wid;   // 896 blocks -> 7168 jobs = 3584 rows x 2 halves
    const int half = job & 1;
    const int row  = job >> 1;               // 0..3583
    const int n    = row / HH;
    const int h    = row - n * HH;
    const int ch   = half * 32 + lane;

    u64 wv0 = g_w2b[ch * 9 + 0], wv1 = g_w2b[ch * 9 + 1], wv2 = g_w2b[ch * 9 + 2];
    u64 wv3 = g_w2b[ch * 9 + 3], wv4 = g_w2b[ch * 9 + 4], wv5 = g_w2b[ch * 9 + 5];
    u64 wv6 = g_w2b[ch * 9 + 6], wv7 = g_w2b[ch * 9 + 7], wv8 = g_w2b[ch * 9 + 8];

    const int rowc = (h == 0) ? 1 : ((h == HH - 1) ? 2 : 0);
    const int corr_mid   = g_ctab[(rowc * 3 + 0) * 64 + ch];
    const int corr_left  = g_ctab[(rowc * 3 + 1) * 64 + ch];
    const int corr_right = g_ctab[(rowc * 3 + 2) * 64 + ch];

    // padded rows h, h+1, h+2 == unpadded h-1, h, h+1 (halo physically zero)
    const u64* top = g_a1p + (size_t)n * PADHW + (size_t)h * PADW;
    const u64* mid = top + PADW;
    const u64* bot = mid + PADW;

    u64 t0 = __ldg(top + 0), t1 = __ldg(top + 1);
    u64 m0 = __ldg(mid + 0), m1 = __ldg(mid + 1);
    u64 b0 = __ldg(bot + 0), b1 = __ldg(bot + 1);

    short* orow = g_s2 + (size_t)(n * HW + h * WW) * 64 + ch;
    int acc_s = 0, acc_q = 0;

    #pragma unroll 2
    for (int w = 0; w < WW; w++) {
        u64 t2 = __ldg(top + w + 2);
        u64 m2 = __ldg(mid + w + 2);
        u64 b2 = __ldg(bot + w + 2);
        int d = __popcll(t0 ^ wv0) + __popcll(t1 ^ wv1) + __popcll(t2 ^ wv2)
              + __popcll(m0 ^ wv3) + __popcll(m1 ^ wv4) + __popcll(m2 ^ wv5)
              + __popcll(b0 ^ wv6) + __popcll(b1 ^ wv7) + __popcll(b2 ^ wv8);
        int corr = (w == 0) ? corr_left : ((w == WW - 1) ? corr_right : corr_mid);
        int s = 576 - 2 * d - corr;
        acc_s += s;
        acc_q += s * s;
        orow[(size_t)w * 64] = (short)s;
        t0 = t1; t1 = t2; m0 = m1; m1 = m2; b0 = b1; b1 = b2;
    }

    atomicAdd(&bsum[ch], acc_s);
    atomicAdd(&bsq[ch],  acc_q);
    __syncthreads();
    if (tid < 64) {
        atomicAdd((u64*)&g_sum2[tid], (u64)(long long)bsum[tid]);
        atomicAdd((u64*)&g_ss2[tid],  (u64)(long long)bsq[tid]);
    }
}

// ---------------- K4a: BN2 threshold -> conv3 input bits ----------------
__global__ __launch_bounds__(256) void k4a_pack2(const float* __restrict__ g2,
                                                 const float* __restrict__ b2) {
    __shared__ float As[64], Bs[64];
    const int tid = threadIdx.x;
    if (tid < 64) {
        double m   = (double)g_sum2[tid] / CNTD;
        double var = (double)g_ss2[tid] / CNTD - m * m;
        double r   = rsqrt(var + EPSD);
        double A   = (double)g2[tid] * r;
        As[tid] = (float)A;
        Bs[tid] = (float)((double)b2[tid] - A * m);
    }
    __syncthreads();

    const int p = blockIdx.x * 256 + tid;   // 784 blocks
    const int4* sp = reinterpret_cast<const int4*>(g_s2 + (size_t)p * 64);
    u64 v = 0;
    #pragma unroll
    for (int g = 0; g < 8; g++) {
        int4 qq = sp[g];                    // channels g*8 .. g*8+7
        int arr[4] = {qq.x, qq.y, qq.z, qq.w};
        #pragma unroll
        for (int k = 0; k < 4; k++) {
            const int co = g * 8 + k * 2;
            float lo = (float)(short)arr[k];
            float hi = (float)(short)(arr[k] >> 16);
            v |= (u64)(fmaf(As[co],     lo, Bs[co])     > 0.f) << co;
            v |= (u64)(fmaf(As[co + 1], hi, Bs[co + 1]) > 0.f) << (co + 1);
        }
    }
    reinterpret_cast<u64*>(g_a2)[p] = v;
}

// ---------------- K4b: conv3 stats; thread = channel, register accumulation ----------------
__global__ __launch_bounds__(256) void k4b_stats3() {
    const int tid = threadIdx.x;            // = channel 0..255
    const u64 w = g_w3b[tid];
    const u64* ap = reinterpret_cast<const u64*>(g_a2) + (size_t)blockIdx.x * 256;
    int acc_s = 0, acc_q = 0;
    #pragma unroll 4
    for (int i = 0; i < 256; i++) {
        int t = 64 - 2 * __popcll(__ldg(ap + i) ^ w);
        acc_s += t;
        acc_q += t * t;
    }
    atomicAdd((u64*)&g_sum3[tid], (u64)(long long)acc_s);
    atomicAdd((u64*)&g_ss3[tid],  (u64)(long long)acc_q);
}

// ---------------- K5: finalize BN3 affine ----------------
__global__ void k5_fin3(const float* __restrict__ g3, const float* __restrict__ b3) {
    const int c = threadIdx.x;   // 256 threads
    double m   = (double)g_sum3[c] / CNTD;
    double var = (double)g_ss3[c] / CNTD - m * m;
    double r   = rsqrt(var + EPSD);
    double A   = (double)g3[c] * r;
    g_A3[c] = (float)A;
    g_B3[c] = (float)((double)b3[c] - A * m);
}

// ---------------- K6: conv3 recompute + BN3 + residual + hardtanh ----------------
__global__ __launch_bounds__(256) void k6_final(const float* __restrict__ x,
                                                float* __restrict__ out) {
    __shared__ u64 w3s[8];
    __shared__ float As[8], Bs[8];
    const int tid = threadIdx.x;
    const int cg  = blockIdx.y;          // 32 channel groups of 8
    if (tid < 8) {
        w3s[tid] = g_w3b[cg * 8 + tid];
        As[tid]  = g_A3[cg * 8 + tid];
        Bs[tid]  = g_B3[cg * 8 + tid];
    }
    __syncthreads();

    const int q  = blockIdx.x * 256 + tid;   // NQUAD
    const int n  = q / 784;
    const int hw = (q - n * 784) * 4;
    ulonglong4 a = g_a2[q];
    u64 av0 = a.x, av1 = a.y, av2 = a.z, av3 = a.w;

    const size_t base = ((size_t)n * CIN + (size_t)cg * 8) * HW + hw;
    #pragma unroll
    for (int k = 0; k < 8; k++) {
        const u64 wv = w3s[k];
        const float A = As[k], B = Bs[k];
        float4 xv = *reinterpret_cast<const float4*>(x + base + (size_t)k * HW);
        float4 o;
        o.x = fminf(fmaxf(fmaf(A, (float)(64 - 2 * __popcll(av0 ^ wv)), B) + xv.x, -1.f), 1.f);
        o.y = fminf(fmaxf(fmaf(A, (float)(64 - 2 * __popcll(av1 ^ wv)), B) + xv.y, -1.f), 1.f);
        o.z = fminf(fmaxf(fmaf(A, (float)(64 - 2 * __popcll(av2 ^ wv)), B) + xv.z, -1.f), 1.f);
        o.w = fminf(fmaxf(fmaf(A, (float)(64 - 2 * __popcll(av3 ^ wv)), B) + xv.w, -1.f), 1.f);
        *reinterpret_cast<float4*>(out + base + (size_t)k * HW) = o;
    }
}

extern "C" void kernel_launch(void* const* d_in, const int* in_sizes, int n_in,
                              void* d_out, int out_size) {
    const float* x  = (const float*)d_in[0];
    const float* w1 = (const float*)d_in[1];
    const float* w2 = (const float*)d_in[2];
    const float* w3 = (const float*)d_in[3];
    const float* g1 = (const float*)d_in[4];
    const float* b1 = (const float*)d_in[5];
    const float* g2 = (const float*)d_in[6];
    const float* b2 = (const float*)d_in[7];
    const float* g3 = (const float*)d_in[8];
    const float* b3 = (const float*)d_in[9];
    float* out = (float*)d_out;

    k0_init<<<1, 576>>>(w1, w2, w3);
    k1_conv1<<<784, 256>>>(x);
    k2_bnpack1<<<784, 256>>>(g1, b1);
    k3_conv2<<<896, 256>>>();
    k4a_pack2<<<784, 256>>>(g2, b2);
    k4b_stats3<<<784, 256>>>();
    k5_fin3<<<1, 256>>>(g3, b3);
    dim3 g6(196, 32);
    k6_final<<<g6, 256>>>(x, out);
}

// round 5
// speedup vs baseline: 1.1681x; 1.0134x over previous
#include <cuda_runtime.h>
#include <cstdint>

typedef unsigned long long u64;

#define NB    64
#define CIN   256
#define HH    56
#define WW    56
#define HW    3136
#define NPIX  200704   // NB*HW
#define NQUAD 50176    // NPIX/4
#define CNTD  200704.0
#define EPSD  1e-5
#define PADW  58
#define PADHW 3364     // 58*58

// ---------------- static device scratch ----------------
__device__ u64  g_w1b[64 * 4];
__device__ u64  g_w2b[64 * 9];
__device__ u64  g_w3b[256];
__device__ int  g_ctab[9 * 64];       // border-pattern corrections for conv2
__device__ int4 g_s1v[8 * NPIX];      // conv1 outputs int16, [group][pixel]
__device__ short g_s2[NPIX * 64];     // conv2 outputs int16, [pixel][ch]
__device__ u64  g_a1p[NB * PADHW];    // conv2 input bits, zero halo (zero-init, halo never written)
__device__ ulonglong4 g_a2[NQUAD];    // conv3 input bits (pixel-major u64, quad views)
__device__ long long g_sum1[64], g_ss1[64];
__device__ long long g_sum2[64], g_ss2[64];
__device__ long long g_sum3[256], g_ss3[256];
__device__ float g_A3[256], g_B3[256];

// ---------------- K0: zero stats + pack weights + border table ----------------
__global__ void k0_init(const float* __restrict__ w1,
                        const float* __restrict__ w2,
                        const float* __restrict__ w3) {
    const int t = threadIdx.x;   // 576 threads
    if (t < 64) {
        u64 wd0 = 0, wd1 = 0, wd2 = 0, wd3 = 0;
        const float* wp = w1 + t * 256;
        #pragma unroll 8
        for (int c = 0; c < 64; c++) wd0 |= (u64)(wp[c]       > 0.f) << c;
        #pragma unroll 8
        for (int c = 0; c < 64; c++) wd1 |= (u64)(wp[c + 64]  > 0.f) << c;
        #pragma unroll 8
        for (int c = 0; c < 64; c++) wd2 |= (u64)(wp[c + 128] > 0.f) << c;
        #pragma unroll 8
        for (int c = 0; c < 64; c++) wd3 |= (u64)(wp[c + 192] > 0.f) << c;
        g_w1b[t * 4 + 0] = wd0; g_w1b[t * 4 + 1] = wd1;
        g_w1b[t * 4 + 2] = wd2; g_w1b[t * 4 + 3] = wd3;
        g_sum1[t] = 0; g_ss1[t] = 0; g_sum2[t] = 0; g_ss2[t] = 0;
    }
    {   // w2 OIHW (64,64,3,3)
        const int co = t / 9, tap = t - co * 9;
        u64 wd = 0;
        #pragma unroll 8
        for (int ci = 0; ci < 64; ci++)
            wd |= (u64)(w2[(co * 64 + ci) * 9 + tap] > 0.f) << ci;
        g_w2b[t] = wd;
    }
    if (t < 256) {
        u64 wd = 0;
        #pragma unroll 8
        for (int ci = 0; ci < 64; ci++)
            wd |= (u64)(w3[t * 64 + ci] > 0.f) << ci;
        g_w3b[t] = wd;
        g_sum3[t] = 0; g_ss3[t] = 0;
    }
    __syncthreads();
    // Correction table: pattern pid = rowcase*3+colcase; entry = sum over
    // invalid taps of (64 - 2*popc(w2_tap)) (what a zero halo word wrongly adds).
    {
        const int pid = t / 64, co = t - pid * 64;  // t<576 -> pid<9
        const int rowc = pid / 3, colc = pid - rowc * 3;
        int corr = 0;
        #pragma unroll
        for (int tap = 0; tap < 9; tap++) {
            const int r = tap / 3, c = tap - r * 3;
            bool inval = (rowc == 1 && r == 0) || (rowc == 2 && r == 2) ||
                         (colc == 1 && c == 0) || (colc == 2 && c == 2);
            if (inval) corr += 64 - 2 * __popcll(g_w2b[co * 9 + tap]);
        }
        g_ctab[t] = corr;
    }
}

// ---------------- K1: pack x (4 px/thread, float4), conv1, stats ----------------
__global__ __launch_bounds__(128) void k1_conv1(const float* __restrict__ x) {
    __shared__ u64 w1s[256];
    __shared__ int ssum[64], sss[64];
    const int tid = threadIdx.x;
    if (tid < 64) { ssum[tid] = 0; sss[tid] = 0; }
    for (int i = tid; i < 256; i += 128) w1s[i] = g_w1b[i];
    __syncthreads();

    const int q  = blockIdx.x * 128 + tid;   // 392*128 = NQUAD
    const int n  = q / 784;
    const int hw = (q - n * 784) * 4;
    const float* xp = x + (size_t)n * CIN * HW + hw;

    u64 v[4][4];   // [pixel][word]
    #pragma unroll
    for (int wi = 0; wi < 4; wi++) {
        u64 b0 = 0, b1 = 0, b2 = 0, b3 = 0;
        #pragma unroll 8
        for (int c = 0; c < 64; c++) {
            float4 xv = *reinterpret_cast<const float4*>(xp + (size_t)(wi * 64 + c) * HW);
            b0 |= (u64)(xv.x > 0.f) << c;
            b1 |= (u64)(xv.y > 0.f) << c;
            b2 |= (u64)(xv.z > 0.f) << c;
            b3 |= (u64)(xv.w > 0.f) << c;
        }
        v[0][wi] = b0; v[1][wi] = b1; v[2][wi] = b2; v[3][wi] = b3;
    }

    const int lane = tid & 31;

    #pragma unroll 1
    for (int g = 0; g < 8; g++) {
        int pk[4][4];   // [pixel][jj]
        #pragma unroll
        for (int jj = 0; jj < 4; jj++) {
            int sv[4][2];
            #pragma unroll
            for (int k = 0; k < 2; k++) {
                const int co = g * 8 + jj * 2 + k;
                const u64* wq = &w1s[co * 4];
                const u64 q0 = wq[0], q1 = wq[1], q2 = wq[2], q3 = wq[3];
                int stot = 0, qtot = 0;
                #pragma unroll
                for (int j = 0; j < 4; j++) {
                    int d = __popcll(v[j][0] ^ q0) + __popcll(v[j][1] ^ q1)
                          + __popcll(v[j][2] ^ q2) + __popcll(v[j][3] ^ q3);
                    int s = 256 - 2 * d;
                    sv[j][k] = s; stot += s; qtot += s * s;
                }
                int rs = __reduce_add_sync(0xFFFFFFFFu, stot);
                int rq = __reduce_add_sync(0xFFFFFFFFu, qtot);
                if (lane == 0) { atomicAdd(&ssum[co], rs); atomicAdd(&sss[co], rq); }
            }
            #pragma unroll
            for (int j = 0; j < 4; j++)
                pk[j][jj] = (sv[j][0] & 0xFFFF) | (sv[j][1] << 16);
        }
        #pragma unroll
        for (int j = 0; j < 4; j++)
            g_s1v[(size_t)g * NPIX + 4 * q + j] = make_int4(pk[j][0], pk[j][1], pk[j][2], pk[j][3]);
    }
    __syncthreads();
    if (tid < 64) {
        atomicAdd((u64*)&g_sum1[tid], (u64)(long long)ssum[tid]);
        atomicAdd((u64*)&g_ss1[tid],  (u64)(long long)sss[tid]);
    }
}

// ---------------- K2: BN1 threshold -> padded conv2 input bits ----------------
__global__ __launch_bounds__(256) void k2_bnpack1(const float* __restrict__ g1,
                                                  const float* __restrict__ b1) {
    __shared__ float As[64], Bs[64];
    const int tid = threadIdx.x;
    if (tid < 64) {
        double m   = (double)g_sum1[tid] / CNTD;
        double var = (double)g_ss1[tid] / CNTD - m * m;
        double r   = rsqrt(var + EPSD);
        double A   = (double)g1[tid] * r;
        As[tid] = (float)A;
        Bs[tid] = (float)((double)b1[tid] - A * m);
    }
    __syncthreads();
    const int p = blockIdx.x * 256 + tid;
    u64 v = 0;
    #pragma unroll
    for (int g = 0; g < 8; g++) {
        int4 q = g_s1v[(size_t)g * NPIX + p];
        int arr[4] = {q.x, q.y, q.z, q.w};
        #pragma unroll
        for (int k = 0; k < 4; k++) {
            const int co = g * 8 + k * 2;
            float lo = (float)(short)arr[k];
            float hi = (float)(short)(arr[k] >> 16);
            v |= (u64)(fmaf(As[co],     lo, Bs[co])     > 0.f) << co;
            v |= (u64)(fmaf(As[co + 1], hi, Bs[co + 1]) > 0.f) << (co + 1);
        }
    }
    const int n  = p / HW;
    const int hw = p - n * HW;
    const int h  = hw / WW;
    const int w  = hw - h * WW;
    g_a1p[(size_t)n * PADHW + (size_t)(h + 1) * PADW + (w + 1)] = v;
}

// ---------------- K3: conv2 (3x3, pad 1) + stats ----------------
// Warp = (row-pair, channel-half). Lane = channel: 9 weights in registers.
// Software pipeline: per 4-pixel chunk, 16 batched loads then pure popc ALU
// for 2 output rows (doubled ILP, 2 loads per output pixel).
__global__ __launch_bounds__(256) void k3_conv2() {
    __shared__ int bsum[64], bsq[64];
    const int tid  = threadIdx.x;
    const int wid  = tid >> 5;
    const int lane = tid & 31;
    if (tid < 64) { bsum[tid] = 0; bsq[tid] = 0; }
    __syncthreads();

    const int job  = blockIdx.x * 8 + wid;   // 448 blocks * 8 = 3584 jobs
    const int half = job & 1;
    const int pr   = job >> 1;               // 1792 row pairs
    const int n    = pr / 28;
    const int hp   = (pr - n * 28) * 2;      // top output row (even)
    const int ch   = half * 32 + lane;

    u64 wv[9];
    #pragma unroll
    for (int t = 0; t < 9; t++) wv[t] = g_w2b[ch * 9 + t];

    const int rowcT = (hp == 0) ? 1 : 0;
    const int rowcB = (hp + 1 == HH - 1) ? 2 : 0;
    const int cT_m = g_ctab[(rowcT * 3 + 0) * 64 + ch];
    const int cT_l = g_ctab[(rowcT * 3 + 1) * 64 + ch];
    const int cT_r = g_ctab[(rowcT * 3 + 2) * 64 + ch];
    const int cB_m = g_ctab[(rowcB * 3 + 0) * 64 + ch];
    const int cB_l = g_ctab[(rowcB * 3 + 1) * 64 + ch];
    const int cB_r = g_ctab[(rowcB * 3 + 2) * 64 + ch];

    // padded rows hp..hp+3 = unpadded hp-1..hp+2 (halo physically zero)
    const u64* r0 = g_a1p + (size_t)n * PADHW + (size_t)hp * PADW;
    const u64* r1 = r0 + PADW;
    const u64* r2 = r1 + PADW;
    const u64* r3 = r2 + PADW;

    u64 a0[6], a1[6], a2[6], a3[6];
    a0[0] = __ldg(r0 + 0); a0[1] = __ldg(r0 + 1);
    a1[0] = __ldg(r1 + 0); a1[1] = __ldg(r1 + 1);
    a2[0] = __ldg(r2 + 0); a2[1] = __ldg(r2 + 1);
    a3[0] = __ldg(r3 + 0); a3[1] = __ldg(r3 + 1);

    short* oT = g_s2 + (size_t)(n * HW + hp * WW) * 64 + ch;
    short* oB = oT + (size_t)WW * 64;
    int accsT = 0, accqT = 0, accsB = 0, accqB = 0;

    #pragma unroll 1
    for (int c = 0; c < 14; c++) {
        const int base = c * 4;
        #pragma unroll
        for (int j = 0; j < 4; j++) {
            a0[2 + j] = __ldg(r0 + base + 2 + j);
            a1[2 + j] = __ldg(r1 + base + 2 + j);
            a2[2 + j] = __ldg(r2 + base + 2 + j);
            a3[2 + j] = __ldg(r3 + base + 2 + j);
        }
        #pragma unroll
        for (int j = 0; j < 4; j++) {
            const int w = base + j;
            int dT = __popcll(a0[j] ^ wv[0]) + __popcll(a0[j+1] ^ wv[1]) + __popcll(a0[j+2] ^ wv[2])
                   + __popcll(a1[j] ^ wv[3]) + __popcll(a1[j+1] ^ wv[4]) + __popcll(a1[j+2] ^ wv[5])
                   + __popcll(a2[j] ^ wv[6]) + __popcll(a2[j+1] ^ wv[7]) + __popcll(a2[j+2] ^ wv[8]);
            int dB = __popcll(a1[j] ^ wv[0]) + __popcll(a1[j+1] ^ wv[1]) + __popcll(a1[j+2] ^ wv[2])
                   + __popcll(a2[j] ^ wv[3]) + __popcll(a2[j+1] ^ wv[4]) + __popcll(a2[j+2] ^ wv[5])
                   + __popcll(a3[j] ^ wv[6]) + __popcll(a3[j+1] ^ wv[7]) + __popcll(a3[j+2] ^ wv[8]);
            const int corrT = (w == 0) ? cT_l : ((w == WW - 1) ? cT_r : cT_m);
            const int corrB = (w == 0) ? cB_l : ((w == WW - 1) ? cB_r : cB_m);
            int sT = 576 - 2 * dT - corrT;
            int sB = 576 - 2 * dB - corrB;
            accsT += sT; accqT += sT * sT;
            accsB += sB; accqB += sB * sB;
            oT[(size_t)w * 64] = (short)sT;
            oB[(size_t)w * 64] = (short)sB;
        }
        a0[0] = a0[4]; a0[1] = a0[5];
        a1[0] = a1[4]; a1[1] = a1[5];
        a2[0] = a2[4]; a2[1] = a2[5];
        a3[0] = a3[4]; a3[1] = a3[5];
    }

    atomicAdd(&bsum[ch], accsT + accsB);
    atomicAdd(&bsq[ch],  accqT + accqB);
    __syncthreads();
    if (tid < 64) {
        atomicAdd((u64*)&g_sum2[tid], (u64)(long long)bsum[tid]);
        atomicAdd((u64*)&g_ss2[tid],  (u64)(long long)bsq[tid]);
    }
}

// ---------------- K4: BN2 threshold -> conv3 bits + conv3 stats (fused) ----------------
__global__ __launch_bounds__(256) void k4_pack2_stats3(const float* __restrict__ g2,
                                                       const float* __restrict__ b2) {
    __shared__ float As[64], Bs[64];
    __shared__ u64 vsh[256];
    const int tid = threadIdx.x;
    if (tid < 64) {
        double m   = (double)g_sum2[tid] / CNTD;
        double var = (double)g_ss2[tid] / CNTD - m * m;
        double r   = rsqrt(var + EPSD);
        double A   = (double)g2[tid] * r;
        As[tid] = (float)A;
        Bs[tid] = (float)((double)b2[tid] - A * m);
    }
    __syncthreads();

    const int p = blockIdx.x * 256 + tid;   // 784 blocks
    const int4* sp = reinterpret_cast<const int4*>(g_s2 + (size_t)p * 64);
    u64 v = 0;
    #pragma unroll
    for (int g = 0; g < 8; g++) {
        int4 qq = sp[g];
        int arr[4] = {qq.x, qq.y, qq.z, qq.w};
        #pragma unroll
        for (int k = 0; k < 4; k++) {
            const int co = g * 8 + k * 2;
            float lo = (float)(short)arr[k];
            float hi = (float)(short)(arr[k] >> 16);
            v |= (u64)(fmaf(As[co],     lo, Bs[co])     > 0.f) << co;
            v |= (u64)(fmaf(As[co + 1], hi, Bs[co + 1]) > 0.f) << (co + 1);
        }
    }
    reinterpret_cast<u64*>(g_a2)[p] = v;
    vsh[tid] = v;
    __syncthreads();

    // phase 2: thread = conv3 output channel
    const u64 w = g_w3b[tid];
    int acc_s = 0, acc_q = 0;
    #pragma unroll 8
    for (int i = 0; i < 256; i++) {
        int t = 64 - 2 * __popcll(vsh[i] ^ w);
        acc_s += t;
        acc_q += t * t;
    }
    atomicAdd((u64*)&g_sum3[tid], (u64)(long long)acc_s);
    atomicAdd((u64*)&g_ss3[tid],  (u64)(long long)acc_q);
}

// ---------------- K5: finalize BN3 affine ----------------
__global__ void k5_fin3(const float* __restrict__ g3, const float* __restrict__ b3) {
    const int c = threadIdx.x;   // 256 threads
    double m   = (double)g_sum3[c] / CNTD;
    double var = (double)g_ss3[c] / CNTD - m * m;
    double r   = rsqrt(var + EPSD);
    double A   = (double)g3[c] * r;
    g_A3[c] = (float)A;
    g_B3[c] = (float)((double)b3[c] - A * m);
}

// ---------------- K6: conv3 recompute + BN3 + residual + hardtanh ----------------
__global__ __launch_bounds__(256) void k6_final(const float* __restrict__ x,
                                                float* __restrict__ out) {
    __shared__ u64 w3s[8];
    __shared__ float As[8], Bs[8];
    const int tid = threadIdx.x;
    const int cg  = blockIdx.y;          // 32 channel groups of 8
    if (tid < 8) {
        w3s[tid] = g_w3b[cg * 8 + tid];
        As[tid]  = g_A3[cg * 8 + tid];
        Bs[tid]  = g_B3[cg * 8 + tid];
    }
    __syncthreads();

    const int q  = blockIdx.x * 256 + tid;   // NQUAD
    const int n  = q / 784;
    const int hw = (q - n * 784) * 4;
    ulonglong4 a = g_a2[q];
    u64 av0 = a.x, av1 = a.y, av2 = a.z, av3 = a.w;

    const size_t base = ((size_t)n * CIN + (size_t)cg * 8) * HW + hw;
    #pragma unroll
    for (int k = 0; k < 8; k++) {
        const u64 wv = w3s[k];
        const float A = As[k], B = Bs[k];
        float4 xv = *reinterpret_cast<const float4*>(x + base + (size_t)k * HW);
        float4 o;
        o.x = fminf(fmaxf(fmaf(A, (float)(64 - 2 * __popcll(av0 ^ wv)), B) + xv.x, -1.f), 1.f);
        o.y = fminf(fmaxf(fmaf(A, (float)(64 - 2 * __popcll(av1 ^ wv)), B) + xv.y, -1.f), 1.f);
        o.z = fminf(fmaxf(fmaf(A, (float)(64 - 2 * __popcll(av2 ^ wv)), B) + xv.z, -1.f), 1.f);
        o.w = fminf(fmaxf(fmaf(A, (float)(64 - 2 * __popcll(av3 ^ wv)), B) + xv.w, -1.f), 1.f);
        *reinterpret_cast<float4*>(out + base + (size_t)k * HW) = o;
    }
}

extern "C" void kernel_launch(void* const* d_in, const int* in_sizes, int n_in,
                              void* d_out, int out_size) {
    const float* x  = (const float*)d_in[0];
    const float* w1 = (const float*)d_in[1];
    const float* w2 = (const float*)d_in[2];
    const float* w3 = (const float*)d_in[3];
    const float* g1 = (const float*)d_in[4];
    const float* b1 = (const float*)d_in[5];
    const float* g2 = (const float*)d_in[6];
    const float* b2 = (const float*)d_in[7];
    const float* g3 = (const float*)d_in[8];
    const float* b3 = (const float*)d_in[9];
    float* out = (float*)d_out;

    k0_init<<<1, 576>>>(w1, w2, w3);
    k1_conv1<<<392, 128>>>(x);
    k2_bnpack1<<<784, 256>>>(g1, b1);
    k3_conv2<<<448, 256>>>();
    k4_pack2_stats3<<<784, 256>>>(g2, b2);
    k5_fin3<<<1, 256>>>(g3, b3);
    dim3 g6(196, 32);
    k6_final<<<g6, 256>>>(x, out);
}